// round 13
// baseline (speedup 1.0000x reference)
#include <cuda_runtime.h>
#include <cstdint>
#include <cstddef>

#define N_TFH 1000
#define N_TG  20000
#define N_E   4000000
#define NV    (N_E / 4)          // 1,000,000 float4 groups
#define N_TAB (N_TG + N_TFH)     // 21,000 table entries
#define THREADS 640
#define BLOCKS  148
#define SMEM_BYTES (N_TAB * 8)   // float2 table: 168,000 B

// Cross-block reduction state; zero at every entry (last block restores it).
__device__ float    g_sum;
__device__ unsigned g_ticket;

__device__ __forceinline__ float warp_reduce(float v) {
    #pragma unroll
    for (int o = 16; o > 0; o >>= 1)
        v += __shfl_xor_sync(0xFFFFFFFFu, v, o);
    return v;
}

// FFMA-pipe reciprocal: bit-magic seed + 2 Newton iterations. No MUFU.
__device__ __forceinline__ float fast_rcp(float x) {
    float r = __int_as_float(0x7EF311C3 - __float_as_int(x));
    r = r * fmaf(-x, r, 2.0f);
    r = r * fmaf(-x, r, 2.0f);
    return r;
}

// FFMA-pipe natural log (njuffa-style), ~1e-7 rel. No MUFU.
__device__ __forceinline__ float fast_logf(float a) {
    int e = (__float_as_int(a) - 0x3f2aaaab) & 0xff800000;
    float m = __int_as_float(__float_as_int(a) - e);   // m in [2/3, 4/3)
    float i = (float)e * 1.19209290e-7f;
    float f = m - 1.0f;
    float s = f * f;
    float r = fmaf(0.230836749f, f, -0.279208571f);
    float t = fmaf(0.331826031f, f, -0.498910338f);
    r = fmaf(r, s, t);
    r = fmaf(r, s, f);
    r = fmaf(i, 0.693147182f, r);
    return r;
}

struct Group {
    float4 ke, al, cv, ey, ex;
    int4 itg, ith, ieg, ih;
};

__device__ __forceinline__ Group load_group(
    int v,
    const float4* __restrict__ k_edge, const float4* __restrict__ alpha,
    const float4* __restrict__ cov,    const float4* __restrict__ edge_y,
    const float4* __restrict__ edge_x, const int4* __restrict__ idx_tf_tg,
    const int4* __restrict__ idx_tf_high, const int4* __restrict__ edge_tg_idx,
    const int4* __restrict__ is_high)
{
    Group g;
    g.ke  = k_edge[v];      g.al  = alpha[v];
    g.cv  = cov[v];         g.ey  = edge_y[v];
    g.ex  = edge_x[v];      g.itg = idx_tf_tg[v];
    g.ith = idx_tf_high[v]; g.ieg = edge_tg_idx[v];
    g.ih  = is_high[v];
    return g;
}

__device__ __forceinline__ float compute_group(const Group& g,
                                               const float2* s_tab) {
    const float HALF_LOG2PI = 0.918938533204672742f;
    const float* kef = &g.ke.x; const float* alf = &g.al.x;
    const float* cvf = &g.cv.x; const float* eyf = &g.ey.x;
    const float* exf = &g.ex.x;
    const int* itgf = &g.itg.x; const int* ithf = &g.ith.x;
    const int* iegf = &g.ieg.x; const int* ihf  = &g.ih.x;

    float acc = 0.0f;
    #pragma unroll
    for (int l = 0; l < 4; l++) {
        int tfi = ihf[l] ? (N_TG + ithf[l]) : itgf[l];
        float2 tf = s_tab[tfi];          // (tf_mu, tf_sig^2)
        float2 tg = s_tab[iegf[l]];      // (tg_mu, tg_sig^2)

        float iv  = fast_rcp(tf.y);
        float loc = fmaf(kef[l] * cvf[l], (eyf[l] - tf.x) * iv, tg.x);
        loc = fmaxf(loc, 0.0f) + 0.01f;
        float var = fmaf(-alf[l] * alf[l], iv, tg.y);
        var = fmaxf(var, 0.0f) + 0.01f;

        float dx = exf[l] - loc;
        // -logprob = 0.5*(dx^2/var + log(var)) + 0.5*log(2pi)
        acc += fmaf(0.5f, fmaf(dx * dx, fast_rcp(var), fast_logf(var)),
                    HALF_LOG2PI);
    }
    return acc;
}

__global__ __launch_bounds__(THREADS, 1)
void fused_loss_kernel(
    const float* __restrict__ TF_high_mu,
    const float* __restrict__ TF_high_sigma,
    const float* __restrict__ TG_mu,
    const float* __restrict__ TG_sigma,
    const float* __restrict__ TF_high_exp,
    const float* __restrict__ TG_exp,
    const float4* __restrict__ k_edge,
    const float4* __restrict__ alpha,
    const float4* __restrict__ cov,
    const float4* __restrict__ edge_y,
    const float4* __restrict__ edge_x,
    const int*   __restrict__ father_num,
    const int4*  __restrict__ idx_tf_tg,
    const int4*  __restrict__ idx_tf_high,
    const int4*  __restrict__ edge_tg_idx,
    const int4*  __restrict__ is_high,
    float* __restrict__ out)
{
    extern __shared__ float2 s_tab[];   // (mu, sigma^2), fp32, 168 KB
    const float HALF_LOG2PI = 0.918938533204672742f;
    const int tid = threadIdx.x;

    // ---- build (mu, sig^2) table from coalesced reads ----
    for (int i = tid; i < N_TG; i += THREADS) {
        float sg = TG_sigma[i];
        s_tab[i] = make_float2(TG_mu[i], sg * sg);
    }
    for (int i = tid; i < N_TFH; i += THREADS) {
        float sg = TF_high_sigma[i];
        s_tab[N_TG + i] = make_float2(TF_high_mu[i], sg * sg);
    }
    __syncthreads();

    float acc = 0.0f;
    const int gtid   = blockIdx.x * THREADS + tid;
    const int stride = BLOCKS * THREADS;     // 94,720

    // ---- p/q terms (21k elems; exact fp32) ----
    if (gtid < N_TG) {
        float mu = TG_mu[gtid], sg = TG_sigma[gtid], x = TG_exp[gtid];
        float fn = (float)father_num[gtid];
        float z = (x - mu) / sg;
        float lp = -0.5f * z * z - fast_logf(sg) - HALF_LOG2PI;
        acc += (fn - 1.0f) * lp;                           // -q
    }
    if (gtid < N_TFH) {
        float mu = TF_high_mu[gtid], sg = TF_high_sigma[gtid], x = TF_high_exp[gtid];
        float z = (x - mu) / sg;
        acc += 0.5f * z * z + fast_logf(sg) + HALF_LOG2PI; // -p
    }

    // ---- edge term: 2 groups per iteration, 18 LDG.128 in flight ----
    for (int v = gtid; v < NV; v += 2 * stride) {
        const int v2 = v + stride;
        const bool has2 = (v2 < NV);
        const int v2c = has2 ? v2 : v;

        Group ga = load_group(v,   k_edge, alpha, cov, edge_y, edge_x,
                              idx_tf_tg, idx_tf_high, edge_tg_idx, is_high);
        Group gb = load_group(v2c, k_edge, alpha, cov, edge_y, edge_x,
                              idx_tf_tg, idx_tf_high, edge_tg_idx, is_high);

        acc += compute_group(ga, s_tab);
        float accB = compute_group(gb, s_tab);
        if (has2) acc += accB;
    }

    // ---- block reduction -> cross-block self-resetting accumulate ----
    acc = warp_reduce(acc);
    __shared__ float warp_sums[THREADS / 32];
    int lane = tid & 31, wid = tid >> 5;
    if (lane == 0) warp_sums[wid] = acc;
    __syncthreads();
    if (wid == 0) {
        float v = (lane < THREADS / 32) ? warp_sums[lane] : 0.0f;
        v = warp_reduce(v);
        if (lane == 0) {
            atomicAdd(&g_sum, v);
            __threadfence();
            unsigned t = atomicInc(&g_ticket, BLOCKS - 1);  // wraps to 0
            if (t == BLOCKS - 1)
                out[0] = atomicExch(&g_sum, 0.0f);          // publish + reset
        }
    }
}

extern "C" void kernel_launch(void* const* d_in, const int* in_sizes, int n_in,
                              void* d_out, int out_size) {
    cudaFuncSetAttribute(fused_loss_kernel,
                         cudaFuncAttributeMaxDynamicSharedMemorySize, SMEM_BYTES);

    fused_loss_kernel<<<BLOCKS, THREADS, SMEM_BYTES>>>(
        (const float*)d_in[0], (const float*)d_in[1],
        (const float*)d_in[2], (const float*)d_in[3],
        (const float*)d_in[4], (const float*)d_in[5],
        (const float4*)d_in[6], (const float4*)d_in[7],
        (const float4*)d_in[8], (const float4*)d_in[9],
        (const float4*)d_in[10], (const int*)d_in[11],
        (const int4*)d_in[12], (const int4*)d_in[13],
        (const int4*)d_in[14], (const int4*)d_in[15],
        (float*)d_out);
}